// round 13
// baseline (speedup 1.0000x reference)
#include <cuda_runtime.h>
#include <cuda_fp16.h>
#include <math.h>

#define F_IN  32
#define F_H1  16
#define F_H2  8
#define N_CLS 5
#define MAX_N 1048576
#define MAX_E 16000000

typedef unsigned long long u64;

// ---- scratch (__device__ globals; allocation-free rule) ----
__device__ __align__(16) int   g_cnt[MAX_N];          // in-degree
__device__ __align__(16) int   g_off[MAX_N];          // CSR offsets
__device__ __align__(16) int   g_cur[MAX_N];          // fill cursors
__device__ __align__(16) float g_dis[MAX_N];          // rsqrt(deg+1)
__device__ __align__(16) int   g_csr[MAX_E];          // src ids bucketed by dst (dense)
__device__ int g_cursor;                              // CSR region cursor
__device__ __align__(16) uint4 g_h1h[MAX_N * 2];      // fp16: dis*(x@W1), 32B/row
__device__ __align__(16) uint4 g_h2h[MAX_N];          // fp16: dis*(relu(conv1)@W2), 16B/row
__device__ __align__(16) float g_f [MAX_N * F_H2];    // relu(conv2)

__constant__ u64 c_W1p[F_IN * F_H1 / 2];              // W1 as packed f32 pairs

__device__ __forceinline__ u64 pack2(float lo, float hi) {
    u64 r; asm("mov.b64 %0,{%1,%2};" : "=l"(r) : "f"(lo), "f"(hi)); return r;
}
__device__ __forceinline__ void unpack2(u64 v, float& lo, float& hi) {
    asm("mov.b64 {%0,%1},%2;" : "=f"(lo), "=f"(hi) : "l"(v));
}
__device__ __forceinline__ u64 ffma2(u64 a, u64 b, u64 c) {
    u64 d; asm("fma.rn.f32x2 %0,%1,%2,%3;" : "=l"(d) : "l"(a), "l"(b), "l"(c)); return d;
}
__device__ __forceinline__ unsigned h2u(__half2 h) {
    return *reinterpret_cast<unsigned*>(&h);
}

// ------------------------------------------- zero counters + CSR cursor
__global__ void k_zero(int N4) {
    int i = blockIdx.x * blockDim.x + threadIdx.x;
    if (i < N4) reinterpret_cast<int4*>(g_cnt)[i] = make_int4(0, 0, 0, 0);
    if (i == 0) g_cursor = 0;
}

// ------------------------------------------------- in-degree count (int4 loads)
__global__ void k_count(const int* __restrict__ dst, int E) {
    int i = blockIdx.x * blockDim.x + threadIdx.x;
    int E4 = E >> 2;
    if (i < E4) {
        int4 d = reinterpret_cast<const int4*>(dst)[i];
        atomicAdd(&g_cnt[d.x], 1); atomicAdd(&g_cnt[d.y], 1);
        atomicAdd(&g_cnt[d.z], 1); atomicAdd(&g_cnt[d.w], 1);
    } else {
        int b = E4 * 4 + (i - E4);
        if (b < E) atomicAdd(&g_cnt[dst[b]], 1);
    }
}

// ---- single-kernel offsets: local scan + atomic region reservation + dis ----
__global__ __launch_bounds__(1024) void k_offs(int N) {
    __shared__ int s[1024];
    __shared__ int base_s;
    int tid = threadIdx.x;
    int i = blockIdx.x * 1024 + tid;
    int v = (i < N) ? g_cnt[i] : 0;
    s[tid] = v;
    __syncthreads();
    for (int off = 1; off < 1024; off <<= 1) {
        int t = (tid >= off) ? s[tid - off] : 0;
        __syncthreads();
        s[tid] += t;
        __syncthreads();
    }
    if (tid == 1023) base_s = atomicAdd(&g_cursor, s[1023]);
    __syncthreads();
    if (i < N) {
        int excl = s[tid] - v + base_s;
        g_off[i] = excl;
        g_cur[i] = excl;
        g_dis[i] = rsqrtf((float)v + 1.0f);
    }
}

// ---------------------------------------------------------------- CSR fill
__global__ void k_fill(const int* __restrict__ src, const int* __restrict__ dst, int E) {
    int i = blockIdx.x * blockDim.x + threadIdx.x;
    int E4 = E >> 2;
    if (i < E4) {
        int4 d = reinterpret_cast<const int4*>(dst)[i];
        int4 s = reinterpret_cast<const int4*>(src)[i];
        g_csr[atomicAdd(&g_cur[d.x], 1)] = s.x;
        g_csr[atomicAdd(&g_cur[d.y], 1)] = s.y;
        g_csr[atomicAdd(&g_cur[d.z], 1)] = s.z;
        g_csr[atomicAdd(&g_cur[d.w], 1)] = s.w;
    } else {
        int b = E4 * 4 + (i - E4);
        if (b < E) g_csr[atomicAdd(&g_cur[dst[b]], 1)] = src[b];
    }
}

// - h1' = fp16( dis * (x @ W1) ); const-mem weights, self-computed dis, 2 nodes/thr
__global__ __launch_bounds__(256) void k_gemm1(const float* __restrict__ x, int N) {
    int i0 = (blockIdx.x * blockDim.x + threadIdx.x) * 2;
    if (i0 >= N) return;
    int i1 = i0 + 1;
    bool has1 = i1 < N;

    const float4* xr0 = reinterpret_cast<const float4*>(x + (size_t)i0 * F_IN);
    const float4* xr1 = reinterpret_cast<const float4*>(x + (size_t)(has1 ? i1 : i0) * F_IN);
    u64 accA[F_H1 / 2], accB[F_H1 / 2];
#pragma unroll
    for (int j = 0; j < F_H1 / 2; j++) { accA[j] = 0ull; accB[j] = 0ull; }
#pragma unroll
    for (int k4 = 0; k4 < F_IN / 4; k4++) {
        float4 xa = xr0[k4], xb = xr1[k4];
        float as[4] = {xa.x, xa.y, xa.z, xa.w};
        float bs[4] = {xb.x, xb.y, xb.z, xb.w};
#pragma unroll
        for (int kk = 0; kk < 4; kk++) {
            int k = k4 * 4 + kk;
            u64 ab = pack2(as[kk], as[kk]);
            u64 bb = pack2(bs[kk], bs[kk]);
#pragma unroll
            for (int j = 0; j < F_H1 / 2; j++) {
                u64 w = c_W1p[k * (F_H1 / 2) + j];   // constant port, off the L1 path
                accA[j] = ffma2(ab, w, accA[j]);
                accB[j] = ffma2(bb, w, accB[j]);
            }
        }
    }
    float d0 = rsqrtf((float)__ldg(&g_cnt[i0]) + 1.0f);
    {
        __half2 h[8];
#pragma unroll
        for (int j = 0; j < 8; j++) {
            float lo, hi; unpack2(accA[j], lo, hi);
            h[j] = __floats2half2_rn(lo * d0, hi * d0);
        }
        uint4 o0, o1;
        o0.x = h2u(h[0]); o0.y = h2u(h[1]); o0.z = h2u(h[2]); o0.w = h2u(h[3]);
        o1.x = h2u(h[4]); o1.y = h2u(h[5]); o1.z = h2u(h[6]); o1.w = h2u(h[7]);
        g_h1h[(size_t)i0 * 2 + 0] = o0;
        g_h1h[(size_t)i0 * 2 + 1] = o1;
    }
    if (has1) {
        float d1 = rsqrtf((float)__ldg(&g_cnt[i1]) + 1.0f);
        __half2 h[8];
#pragma unroll
        for (int j = 0; j < 8; j++) {
            float lo, hi; unpack2(accB[j], lo, hi);
            h[j] = __floats2half2_rn(lo * d1, hi * d1);
        }
        uint4 o0, o1;
        o0.x = h2u(h[0]); o0.y = h2u(h[1]); o0.z = h2u(h[2]); o0.w = h2u(h[3]);
        o1.x = h2u(h[4]); o1.y = h2u(h[5]); o1.z = h2u(h[6]); o1.w = h2u(h[7]);
        g_h1h[(size_t)i1 * 2 + 0] = o0;
        g_h1h[(size_t)i1 * 2 + 1] = o1;
    }
}

__device__ __forceinline__ void acc8(float* acc, uint4 raw) {
    const __half2* hp = reinterpret_cast<const __half2*>(&raw);
#pragma unroll
    for (int q = 0; q < 4; q++) {
        float2 f = __half22float2(hp[q]);
        acc[2 * q]     += f.x;
        acc[2 * q + 1] += f.y;
    }
}

// ---- layer-1 aggregation (fp16 gather) + epilogue + relu + GEMM2 fused ----
// 2 lanes per node; epilogue writes fp16 h2 row (uint2 per lane, coalesced)
__global__ __launch_bounds__(256) void k_agg1(const float* __restrict__ b1,
                                              const float* __restrict__ W2, int N) {
    __shared__ float W2s[F_H1 * F_H2];
    __shared__ float b1s[F_H1];
    for (int t = threadIdx.x; t < F_H1 * F_H2; t += blockDim.x) W2s[t] = W2[t];
    if (threadIdx.x < F_H1) b1s[threadIdx.x] = b1[threadIdx.x];
    __syncthreads();

    int t = blockIdx.x * blockDim.x + threadIdx.x;
    int node = t >> 1, sub = t & 1;
    int nodec = node < N ? node : N - 1;     // keep full warp for shuffles

    int beg = __ldg(&g_off[nodec]), cnt = __ldg(&g_cnt[nodec]);
    float acc[8];
#pragma unroll
    for (int j = 0; j < 8; j++) acc[j] = 0.f;
    acc8(acc, __ldg(&g_h1h[(size_t)nodec * 2 + sub]));          // self loop

    int k = 0;
    for (; k + 4 <= cnt; k += 4) {
        int s0 = __ldg(&g_csr[beg + k]),     s1 = __ldg(&g_csr[beg + k + 1]);
        int s2 = __ldg(&g_csr[beg + k + 2]), s3 = __ldg(&g_csr[beg + k + 3]);
        uint4 v0 = __ldg(&g_h1h[(size_t)s0 * 2 + sub]);
        uint4 v1 = __ldg(&g_h1h[(size_t)s1 * 2 + sub]);
        uint4 v2 = __ldg(&g_h1h[(size_t)s2 * 2 + sub]);
        uint4 v3 = __ldg(&g_h1h[(size_t)s3 * 2 + sub]);
        acc8(acc, v0); acc8(acc, v1); acc8(acc, v2); acc8(acc, v3);
    }
    for (; k < cnt; k++) {
        int s = __ldg(&g_csr[beg + k]);
        acc8(acc, __ldg(&g_h1h[(size_t)s * 2 + sub]));
    }

    float dd = g_dis[nodec];
    float own[8];
#pragma unroll
    for (int j = 0; j < 8; j++)
        own[j] = fmaxf(acc[j] * dd + b1s[sub * 8 + j], 0.f);

    // exchange halves with partner lane (same node) -> full 16-vector
    float r[F_H1];
#pragma unroll
    for (int j = 0; j < 8; j++) {
        float oth = __shfl_xor_sync(0xffffffffu, own[j], 1);
        r[sub * 8 + j]       = own[j];
        r[(sub ^ 1) * 8 + j] = oth;
    }
    // each lane computes 4 of the 8 GEMM2 outputs, scaled by dis, packed fp16
    float o[4];
#pragma unroll
    for (int q = 0; q < 4; q++) o[q] = 0.f;
#pragma unroll
    for (int j = 0; j < F_H1; j++) {
#pragma unroll
        for (int q = 0; q < 4; q++)
            o[q] += r[j] * W2s[j * F_H2 + sub * 4 + q];
    }
    if (node < N) {
        uint2 w;
        w.x = h2u(__floats2half2_rn(o[0] * dd, o[1] * dd));
        w.y = h2u(__floats2half2_rn(o[2] * dd, o[3] * dd));
        reinterpret_cast<uint2*>(&g_h2h[node])[sub] = w;
    }
}

// ---- layer-2 aggregation (fp16 gather, 1 lane/node) + epilogue + relu ----
__global__ __launch_bounds__(256) void k_agg2(const float* __restrict__ b2, int N) {
    int node = blockIdx.x * blockDim.x + threadIdx.x;
    if (node >= N) return;
    float b2r[F_H2];
#pragma unroll
    for (int j = 0; j < F_H2; j++) b2r[j] = __ldg(&b2[j]);

    int beg = __ldg(&g_off[node]), cnt = __ldg(&g_cnt[node]);
    float acc[8];
#pragma unroll
    for (int j = 0; j < 8; j++) acc[j] = 0.f;
    acc8(acc, __ldg(&g_h2h[node]));                    // self loop

    int k = 0;
    for (; k + 4 <= cnt; k += 4) {
        int s0 = __ldg(&g_csr[beg + k]),     s1 = __ldg(&g_csr[beg + k + 1]);
        int s2 = __ldg(&g_csr[beg + k + 2]), s3 = __ldg(&g_csr[beg + k + 3]);
        uint4 v0 = __ldg(&g_h2h[s0]);
        uint4 v1 = __ldg(&g_h2h[s1]);
        uint4 v2 = __ldg(&g_h2h[s2]);
        uint4 v3 = __ldg(&g_h2h[s3]);
        acc8(acc, v0); acc8(acc, v1); acc8(acc, v2); acc8(acc, v3);
    }
    for (; k < cnt; k++) {
        int s = __ldg(&g_csr[beg + k]);
        acc8(acc, __ldg(&g_h2h[s]));
    }
    float dd = g_dis[node];
    float4 oa, ob;
    oa.x = fmaxf(acc[0] * dd + b2r[0], 0.f);
    oa.y = fmaxf(acc[1] * dd + b2r[1], 0.f);
    oa.z = fmaxf(acc[2] * dd + b2r[2], 0.f);
    oa.w = fmaxf(acc[3] * dd + b2r[3], 0.f);
    ob.x = fmaxf(acc[4] * dd + b2r[4], 0.f);
    ob.y = fmaxf(acc[5] * dd + b2r[5], 0.f);
    ob.z = fmaxf(acc[6] * dd + b2r[6], 0.f);
    ob.w = fmaxf(acc[7] * dd + b2r[7], 0.f);
    float4* out = reinterpret_cast<float4*>(&g_f[(size_t)node * F_H2]);
    out[0] = oa; out[1] = ob;
}

// ---------------- mean pool (warp per graph, sorted batch) + linear head ----
__global__ __launch_bounds__(256) void k_pool(const int* __restrict__ batch,
                                              const float* __restrict__ Wl,
                                              const float* __restrict__ bl,
                                              float* __restrict__ out, int N, int G) {
    int gw   = (blockIdx.x * blockDim.x + threadIdx.x) >> 5;
    int lane = threadIdx.x & 31;
    if (gw >= G) return;

    int lo = 0, hi = N;
    while (lo < hi) { int m = (lo + hi) >> 1; if (batch[m] <  gw) lo = m + 1; else hi = m; }
    int beg = lo;
    lo = beg; hi = N;
    while (lo < hi) { int m = (lo + hi) >> 1; if (batch[m] <= gw) lo = m + 1; else hi = m; }
    int end = lo;

    float acc[F_H2];
#pragma unroll
    for (int j = 0; j < F_H2; j++) acc[j] = 0.f;

    for (int i = beg + lane; i < end; i += 32) {
        const float4* f4 = reinterpret_cast<const float4*>(&g_f[(size_t)i * F_H2]);
        float4 a = f4[0], b = f4[1];
        acc[0] += a.x; acc[1] += a.y; acc[2] += a.z; acc[3] += a.w;
        acc[4] += b.x; acc[5] += b.y; acc[6] += b.z; acc[7] += b.w;
    }
#pragma unroll
    for (int j = 0; j < F_H2; j++)
#pragma unroll
        for (int off = 16; off; off >>= 1)
            acc[j] += __shfl_xor_sync(0xffffffffu, acc[j], off);

    float inv = 1.0f / fmaxf((float)(end - beg), 1.0f);
    if (lane < N_CLS) {
        float o = bl[lane];
#pragma unroll
        for (int j = 0; j < F_H2; j++) o += (acc[j] * inv) * Wl[j * N_CLS + lane];
        out[(size_t)gw * N_CLS + lane] = o;
    }
}

// ---------------------------------------------------------------- launch
extern "C" void kernel_launch(void* const* d_in, const int* in_sizes, int n_in,
                              void* d_out, int out_size) {
    const float* x     = (const float*)d_in[0];
    const int*   ei    = (const int*)  d_in[1];
    const int*   batch = (const int*)  d_in[2];
    int base = (n_in >= 10 && in_sizes[3] <= 4) ? 4 : 3;
    const float* W1 = (const float*)d_in[base + 0];
    const float* b1 = (const float*)d_in[base + 1];
    const float* W2 = (const float*)d_in[base + 2];
    const float* b2 = (const float*)d_in[base + 3];
    const float* Wl = (const float*)d_in[base + 4];
    const float* bl = (const float*)d_in[base + 5];
    float* out = (float*)d_out;

    int N = in_sizes[2];
    int E = in_sizes[1] / 2;
    int G = out_size / N_CLS;
    const int* src = ei;
    const int* dst = ei + E;

    // one-time host-side resources for the fork-join (no device memory)
    static cudaStream_t s2 = nullptr;
    static cudaEvent_t evA = nullptr, evB = nullptr;
    if (!s2) {
        cudaStreamCreateWithFlags(&s2, cudaStreamNonBlocking);
        cudaEventCreateWithFlags(&evA, cudaEventDisableTiming);
        cudaEventCreateWithFlags(&evB, cudaEventDisableTiming);
    }

    const int T = 256;
    int N4   = (N + 3) / 4;
    int E4   = (E >> 2) + 4;                 // vec body + scalar tail threads
    int ebv  = (E4 + T - 1) / T;
    int NB   = (N + 1023) / 1024;

    // main chain: zero -> count -> (fork) -> offs -> fill
    k_zero <<<(N4 + T - 1) / T, T>>>(N4);
    k_count<<<ebv, T>>>(dst, E);

    cudaEventRecord(evA, 0);
    cudaStreamWaitEvent(s2, evA, 0);
    // side chain (needs only counts + c_W1p): gemm1 (computes its own dis)
    cudaMemcpyToSymbolAsync(c_W1p, W1, F_IN * F_H1 * sizeof(float), 0,
                            cudaMemcpyDeviceToDevice, s2);
    k_gemm1<<<(N + 511) / 512, T, 0, s2>>>(x, N);
    cudaEventRecord(evB, s2);

    k_offs<<<NB, 1024>>>(N);
    k_fill<<<ebv, T>>>(src, dst, E);

    // join: aggregation needs both CSR (main) and h1 (side)
    cudaStreamWaitEvent(0, evB, 0);
    k_agg1<<<((size_t)N * 2 + T - 1) / T, T>>>(b1, W2, N);
    k_agg2<<<((size_t)N + T - 1) / T, T>>>(b2, N);
    k_pool<<<((size_t)G * 32 + T - 1) / T, T>>>(batch, Wl, bl, out, N, G);
}

// round 14
// speedup vs baseline: 1.0002x; 1.0002x over previous
#include <cuda_runtime.h>
#include <cuda_fp16.h>
#include <math.h>

#define F_IN  32
#define F_H1  16
#define F_H2  8
#define N_CLS 5
#define MAX_N 1048576
#define MAX_E 16000000
#define CSR_MAX (MAX_E + 4 * MAX_N)   // room for <=3 pad slots per node

typedef unsigned long long u64;

// ---- scratch (__device__ globals; allocation-free rule) ----
__device__ __align__(16) int   g_cnt[MAX_N];          // in-degree
__device__ __align__(16) int   g_off[MAX_N];          // CSR offsets (4-aligned regions)
__device__ __align__(16) int   g_cur[MAX_N];          // fill cursors
__device__ __align__(16) float g_dis[MAX_N];          // rsqrt(deg+1)
__device__ __align__(16) int   g_csr[CSR_MAX];        // src ids bucketed by dst
__device__ int g_cursor;                              // CSR region cursor
__device__ __align__(16) uint4 g_h1h[MAX_N * 2];      // fp16: dis*(x@W1), 32B/row
__device__ __align__(16) float g_h2[MAX_N * F_H2];    // fp32: dis*(relu(conv1)@W2)
__device__ __align__(16) float g_f [MAX_N * F_H2];    // relu(conv2)

__constant__ u64 c_W1p[F_IN * F_H1 / 2];              // W1 as packed f32 pairs

__device__ __forceinline__ u64 pack2(float lo, float hi) {
    u64 r; asm("mov.b64 %0,{%1,%2};" : "=l"(r) : "f"(lo), "f"(hi)); return r;
}
__device__ __forceinline__ void unpack2(u64 v, float& lo, float& hi) {
    asm("mov.b64 {%0,%1},%2;" : "=f"(lo), "=f"(hi) : "l"(v));
}
__device__ __forceinline__ u64 ffma2(u64 a, u64 b, u64 c) {
    u64 d; asm("fma.rn.f32x2 %0,%1,%2,%3;" : "=l"(d) : "l"(a), "l"(b), "l"(c)); return d;
}
__device__ __forceinline__ unsigned h2u(__half2 h) {
    return *reinterpret_cast<unsigned*>(&h);
}

// ------------------------------------------- zero counters + CSR cursor
__global__ void k_zero(int N4) {
    int i = blockIdx.x * blockDim.x + threadIdx.x;
    if (i < N4) reinterpret_cast<int4*>(g_cnt)[i] = make_int4(0, 0, 0, 0);
    if (i == 0) g_cursor = 0;
}

// ------------------------------------------------- in-degree count (int4 loads)
__global__ void k_count(const int* __restrict__ dst, int E) {
    int i = blockIdx.x * blockDim.x + threadIdx.x;
    int E4 = E >> 2;
    if (i < E4) {
        int4 d = reinterpret_cast<const int4*>(dst)[i];
        atomicAdd(&g_cnt[d.x], 1); atomicAdd(&g_cnt[d.y], 1);
        atomicAdd(&g_cnt[d.z], 1); atomicAdd(&g_cnt[d.w], 1);
    } else {
        int b = E4 * 4 + (i - E4);
        if (b < E) atomicAdd(&g_cnt[dst[b]], 1);
    }
}

// ---- single-kernel offsets: scan of 4-ALIGNED counts + atomic reservation ----
// Regions are 4-aligned so aggs can fetch index quads with LDG.128.
__global__ __launch_bounds__(1024) void k_offs(int N) {
    __shared__ int s[1024];
    __shared__ int base_s;
    int tid = threadIdx.x;
    int i = blockIdx.x * 1024 + tid;
    int v  = (i < N) ? g_cnt[i] : 0;
    int va = (v + 3) & ~3;                 // aligned region size
    s[tid] = va;
    __syncthreads();
    for (int off = 1; off < 1024; off <<= 1) {
        int t = (tid >= off) ? s[tid - off] : 0;
        __syncthreads();
        s[tid] += t;
        __syncthreads();
    }
    if (tid == 1023) base_s = atomicAdd(&g_cursor, s[1023]);
    __syncthreads();
    if (i < N) {
        int excl = s[tid] - va + base_s;   // multiple of 4
        g_off[i] = excl;
        g_cur[i] = excl;
        g_dis[i] = rsqrtf((float)v + 1.0f);
    }
}

// ---------------------------------------------------------------- CSR fill
__global__ void k_fill(const int* __restrict__ src, const int* __restrict__ dst, int E) {
    int i = blockIdx.x * blockDim.x + threadIdx.x;
    int E4 = E >> 2;
    if (i < E4) {
        int4 d = reinterpret_cast<const int4*>(dst)[i];
        int4 s = reinterpret_cast<const int4*>(src)[i];
        g_csr[atomicAdd(&g_cur[d.x], 1)] = s.x;
        g_csr[atomicAdd(&g_cur[d.y], 1)] = s.y;
        g_csr[atomicAdd(&g_cur[d.z], 1)] = s.z;
        g_csr[atomicAdd(&g_cur[d.w], 1)] = s.w;
    } else {
        int b = E4 * 4 + (i - E4);
        if (b < E) g_csr[atomicAdd(&g_cur[dst[b]], 1)] = src[b];
    }
}

// - h1' = fp16( dis * (x @ W1) ); const-mem weights, self-computed dis, 2 nodes/thr
__global__ __launch_bounds__(256) void k_gemm1(const float* __restrict__ x, int N) {
    int i0 = (blockIdx.x * blockDim.x + threadIdx.x) * 2;
    if (i0 >= N) return;
    int i1 = i0 + 1;
    bool has1 = i1 < N;

    const float4* xr0 = reinterpret_cast<const float4*>(x + (size_t)i0 * F_IN);
    const float4* xr1 = reinterpret_cast<const float4*>(x + (size_t)(has1 ? i1 : i0) * F_IN);
    u64 accA[F_H1 / 2], accB[F_H1 / 2];
#pragma unroll
    for (int j = 0; j < F_H1 / 2; j++) { accA[j] = 0ull; accB[j] = 0ull; }
#pragma unroll
    for (int k4 = 0; k4 < F_IN / 4; k4++) {
        float4 xa = xr0[k4], xb = xr1[k4];
        float as[4] = {xa.x, xa.y, xa.z, xa.w};
        float bs[4] = {xb.x, xb.y, xb.z, xb.w};
#pragma unroll
        for (int kk = 0; kk < 4; kk++) {
            int k = k4 * 4 + kk;
            u64 ab = pack2(as[kk], as[kk]);
            u64 bb = pack2(bs[kk], bs[kk]);
#pragma unroll
            for (int j = 0; j < F_H1 / 2; j++) {
                u64 w = c_W1p[k * (F_H1 / 2) + j];   // constant port, off the L1 path
                accA[j] = ffma2(ab, w, accA[j]);
                accB[j] = ffma2(bb, w, accB[j]);
            }
        }
    }
    float d0 = rsqrtf((float)__ldg(&g_cnt[i0]) + 1.0f);
    {
        __half2 h[8];
#pragma unroll
        for (int j = 0; j < 8; j++) {
            float lo, hi; unpack2(accA[j], lo, hi);
            h[j] = __floats2half2_rn(lo * d0, hi * d0);
        }
        uint4 o0, o1;
        o0.x = h2u(h[0]); o0.y = h2u(h[1]); o0.z = h2u(h[2]); o0.w = h2u(h[3]);
        o1.x = h2u(h[4]); o1.y = h2u(h[5]); o1.z = h2u(h[6]); o1.w = h2u(h[7]);
        g_h1h[(size_t)i0 * 2 + 0] = o0;
        g_h1h[(size_t)i0 * 2 + 1] = o1;
    }
    if (has1) {
        float d1 = rsqrtf((float)__ldg(&g_cnt[i1]) + 1.0f);
        __half2 h[8];
#pragma unroll
        for (int j = 0; j < 8; j++) {
            float lo, hi; unpack2(accB[j], lo, hi);
            h[j] = __floats2half2_rn(lo * d1, hi * d1);
        }
        uint4 o0, o1;
        o0.x = h2u(h[0]); o0.y = h2u(h[1]); o0.z = h2u(h[2]); o0.w = h2u(h[3]);
        o1.x = h2u(h[4]); o1.y = h2u(h[5]); o1.z = h2u(h[6]); o1.w = h2u(h[7]);
        g_h1h[(size_t)i1 * 2 + 0] = o0;
        g_h1h[(size_t)i1 * 2 + 1] = o1;
    }
}

__device__ __forceinline__ void acc8(float* acc, uint4 raw) {
    const __half2* hp = reinterpret_cast<const __half2*>(&raw);
#pragma unroll
    for (int q = 0; q < 4; q++) {
        float2 f = __half22float2(hp[q]);
        acc[2 * q]     += f.x;
        acc[2 * q + 1] += f.y;
    }
}

// ---- layer-1 aggregation (fp16 gather, int4 index quads) + relu + GEMM2 ----
// 2 lanes per node; each lane owns 8 of the 16 features (one uint4 = 16B).
__global__ __launch_bounds__(256) void k_agg1(const float* __restrict__ b1,
                                              const float* __restrict__ W2, int N) {
    __shared__ float W2s[F_H1 * F_H2];
    __shared__ float b1s[F_H1];
    for (int t = threadIdx.x; t < F_H1 * F_H2; t += blockDim.x) W2s[t] = W2[t];
    if (threadIdx.x < F_H1) b1s[threadIdx.x] = b1[threadIdx.x];
    __syncthreads();

    int t = blockIdx.x * blockDim.x + threadIdx.x;
    int node = t >> 1, sub = t & 1;
    int nodec = node < N ? node : N - 1;     // keep full warp for shuffles

    int beg = __ldg(&g_off[nodec]), cnt = __ldg(&g_cnt[nodec]);
    float acc[8];
#pragma unroll
    for (int j = 0; j < 8; j++) acc[j] = 0.f;
    acc8(acc, __ldg(&g_h1h[(size_t)nodec * 2 + sub]));          // self loop

    const uint4 z4 = make_uint4(0, 0, 0, 0);
    for (int k = 0; k < cnt; k += 4) {
        int4 q = __ldg(reinterpret_cast<const int4*>(&g_csr[beg + k]));  // aligned quad
        uint4 v0 = __ldg(&g_h1h[(size_t)q.x * 2 + sub]);
        uint4 v1 = z4, v2 = z4, v3 = z4;
        if (k + 1 < cnt) v1 = __ldg(&g_h1h[(size_t)q.y * 2 + sub]);
        if (k + 2 < cnt) v2 = __ldg(&g_h1h[(size_t)q.z * 2 + sub]);
        if (k + 3 < cnt) v3 = __ldg(&g_h1h[(size_t)q.w * 2 + sub]);
        acc8(acc, v0); acc8(acc, v1); acc8(acc, v2); acc8(acc, v3);
    }

    float dd = g_dis[nodec];
    float own[8];
#pragma unroll
    for (int j = 0; j < 8; j++)
        own[j] = fmaxf(acc[j] * dd + b1s[sub * 8 + j], 0.f);

    // exchange halves with partner lane (same node) -> full 16-vector
    float r[F_H1];
#pragma unroll
    for (int j = 0; j < 8; j++) {
        float oth = __shfl_xor_sync(0xffffffffu, own[j], 1);
        r[sub * 8 + j]       = own[j];
        r[(sub ^ 1) * 8 + j] = oth;
    }
    // each lane computes 4 of the 8 GEMM2 outputs, scaled by dis
    float o[4];
#pragma unroll
    for (int q = 0; q < 4; q++) o[q] = 0.f;
#pragma unroll
    for (int j = 0; j < F_H1; j++) {
#pragma unroll
        for (int q = 0; q < 4; q++)
            o[q] += r[j] * W2s[j * F_H2 + sub * 4 + q];
    }
    if (node < N) {
        float4 w = make_float4(o[0] * dd, o[1] * dd, o[2] * dd, o[3] * dd);
        *reinterpret_cast<float4*>(&g_h2[(size_t)node * F_H2 + sub * 4]) = w;
    }
}

// ---- layer-2 aggregation (fp32 gather, int4 index quads) + relu ----
__global__ __launch_bounds__(256) void k_agg2(const float* __restrict__ b2, int N) {
    __shared__ float b2s[F_H2];
    if (threadIdx.x < F_H2) b2s[threadIdx.x] = b2[threadIdx.x];
    __syncthreads();
    int t = blockIdx.x * blockDim.x + threadIdx.x;
    int node = t >> 1, sub = t & 1;
    if (node >= N) return;
    int beg = __ldg(&g_off[node]), cnt = __ldg(&g_cnt[node]);
    const float4* h2t = reinterpret_cast<const float4*>(g_h2);
    float4 acc = __ldg(&h2t[(size_t)node * 2 + sub]);           // self loop
    const float4 z4 = make_float4(0.f, 0.f, 0.f, 0.f);
    for (int k = 0; k < cnt; k += 4) {
        int4 q = __ldg(reinterpret_cast<const int4*>(&g_csr[beg + k]));
        float4 v0 = __ldg(&h2t[(size_t)q.x * 2 + sub]);
        float4 v1 = z4, v2 = z4, v3 = z4;
        if (k + 1 < cnt) v1 = __ldg(&h2t[(size_t)q.y * 2 + sub]);
        if (k + 2 < cnt) v2 = __ldg(&h2t[(size_t)q.z * 2 + sub]);
        if (k + 3 < cnt) v3 = __ldg(&h2t[(size_t)q.w * 2 + sub]);
        acc.x += v0.x + v1.x + v2.x + v3.x;
        acc.y += v0.y + v1.y + v2.y + v3.y;
        acc.z += v0.z + v1.z + v2.z + v3.z;
        acc.w += v0.w + v1.w + v2.w + v3.w;
    }
    float dd = g_dis[node];
    float4 o;
    o.x = fmaxf(acc.x * dd + b2s[sub * 4 + 0], 0.f);
    o.y = fmaxf(acc.y * dd + b2s[sub * 4 + 1], 0.f);
    o.z = fmaxf(acc.z * dd + b2s[sub * 4 + 2], 0.f);
    o.w = fmaxf(acc.w * dd + b2s[sub * 4 + 3], 0.f);
    *reinterpret_cast<float4*>(&g_f[(size_t)node * F_H2 + sub * 4]) = o;
}

// ---------------- mean pool (warp per graph, sorted batch) + linear head ----
__global__ __launch_bounds__(256) void k_pool(const int* __restrict__ batch,
                                              const float* __restrict__ Wl,
                                              const float* __restrict__ bl,
                                              float* __restrict__ out, int N, int G) {
    int gw   = (blockIdx.x * blockDim.x + threadIdx.x) >> 5;
    int lane = threadIdx.x & 31;
    if (gw >= G) return;

    int lo = 0, hi = N;
    while (lo < hi) { int m = (lo + hi) >> 1; if (batch[m] <  gw) lo = m + 1; else hi = m; }
    int beg = lo;
    lo = beg; hi = N;
    while (lo < hi) { int m = (lo + hi) >> 1; if (batch[m] <= gw) lo = m + 1; else hi = m; }
    int end = lo;

    float acc[F_H2];
#pragma unroll
    for (int j = 0; j < F_H2; j++) acc[j] = 0.f;

    for (int i = beg + lane; i < end; i += 32) {
        const float4* f4 = reinterpret_cast<const float4*>(&g_f[(size_t)i * F_H2]);
        float4 a = f4[0], b = f4[1];
        acc[0] += a.x; acc[1] += a.y; acc[2] += a.z; acc[3] += a.w;
        acc[4] += b.x; acc[5] += b.y; acc[6] += b.z; acc[7] += b.w;
    }
#pragma unroll
    for (int j = 0; j < F_H2; j++)
#pragma unroll
        for (int off = 16; off; off >>= 1)
            acc[j] += __shfl_xor_sync(0xffffffffu, acc[j], off);

    float inv = 1.0f / fmaxf((float)(end - beg), 1.0f);
    if (lane < N_CLS) {
        float o = bl[lane];
#pragma unroll
        for (int j = 0; j < F_H2; j++) o += (acc[j] * inv) * Wl[j * N_CLS + lane];
        out[(size_t)gw * N_CLS + lane] = o;
    }
}

// ---------------------------------------------------------------- launch
extern "C" void kernel_launch(void* const* d_in, const int* in_sizes, int n_in,
                              void* d_out, int out_size) {
    const float* x     = (const float*)d_in[0];
    const int*   ei    = (const int*)  d_in[1];
    const int*   batch = (const int*)  d_in[2];
    int base = (n_in >= 10 && in_sizes[3] <= 4) ? 4 : 3;
    const float* W1 = (const float*)d_in[base + 0];
    const float* b1 = (const float*)d_in[base + 1];
    const float* W2 = (const float*)d_in[base + 2];
    const float* b2 = (const float*)d_in[base + 3];
    const float* Wl = (const float*)d_in[base + 4];
    const float* bl = (const float*)d_in[base + 5];
    float* out = (float*)d_out;

    int N = in_sizes[2];
    int E = in_sizes[1] / 2;
    int G = out_size / N_CLS;
    const int* src = ei;
    const int* dst = ei + E;

    // one-time host-side resources for the fork-join (no device memory)
    static cudaStream_t s2 = nullptr;
    static cudaEvent_t evA = nullptr, evB = nullptr;
    if (!s2) {
        cudaStreamCreateWithFlags(&s2, cudaStreamNonBlocking);
        cudaEventCreateWithFlags(&evA, cudaEventDisableTiming);
        cudaEventCreateWithFlags(&evB, cudaEventDisableTiming);
    }

    const int T = 256;
    int N4   = (N + 3) / 4;
    int E4   = (E >> 2) + 4;                 // vec body + scalar tail threads
    int ebv  = (E4 + T - 1) / T;
    int NB   = (N + 1023) / 1024;

    // main chain: zero -> count -> (fork) -> offs -> fill
    k_zero <<<(N4 + T - 1) / T, T>>>(N4);
    k_count<<<ebv, T>>>(dst, E);

    cudaEventRecord(evA, 0);
    cudaStreamWaitEvent(s2, evA, 0);
    // side chain (needs only counts + c_W1p): gemm1 (computes its own dis)
    cudaMemcpyToSymbolAsync(c_W1p, W1, F_IN * F_H1 * sizeof(float), 0,
                            cudaMemcpyDeviceToDevice, s2);
    k_gemm1<<<(N + 511) / 512, T, 0, s2>>>(x, N);
    cudaEventRecord(evB, s2);

    k_offs<<<NB, 1024>>>(N);
    k_fill<<<ebv, T>>>(src, dst, E);

    // join: aggregation needs both CSR (main) and h1 (side)
    cudaStreamWaitEvent(0, evB, 0);
    k_agg1<<<((size_t)N * 2 + T - 1) / T, T>>>(b1, W2, N);
    k_agg2<<<((size_t)N * 2 + T - 1) / T, T>>>(b2, N);
    k_pool<<<((size_t)G * 32 + T - 1) / T, T>>>(batch, Wl, bl, out, N, G);
}

// round 15
// speedup vs baseline: 1.0296x; 1.0293x over previous
#include <cuda_runtime.h>
#include <cuda_fp16.h>
#include <math.h>

#define F_IN  32
#define F_H1  16
#define F_H2  8
#define N_CLS 5
#define MAX_N 1048576
#define MAX_E 16000000

typedef unsigned long long u64;

// ---- scratch (__device__ globals; allocation-free rule) ----
__device__ __align__(16) int   g_cnt[MAX_N];          // in-degree
__device__ __align__(16) int   g_off[MAX_N];          // CSR offsets
__device__ __align__(16) int   g_cur[MAX_N];          // fill cursors
__device__ __align__(16) float g_dis[MAX_N];          // rsqrt(deg+1)
__device__ __align__(16) int   g_csr[MAX_E];          // src ids bucketed by dst (dense)
__device__ int g_cursor;                              // CSR region cursor
__device__ __align__(16) uint4 g_h1h[MAX_N * 2];      // fp16: dis*(x@W1), 32B/row
__device__ __align__(16) uint2 g_h2h[MAX_N * 2];      // fp16: dis*(relu(conv1)@W2), 16B/row
__device__ __align__(16) float g_f [MAX_N * F_H2];    // relu(conv2)

__constant__ u64 c_W1p[F_IN * F_H1 / 2];              // W1 as packed f32 pairs

__device__ __forceinline__ u64 pack2(float lo, float hi) {
    u64 r; asm("mov.b64 %0,{%1,%2};" : "=l"(r) : "f"(lo), "f"(hi)); return r;
}
__device__ __forceinline__ void unpack2(u64 v, float& lo, float& hi) {
    asm("mov.b64 {%0,%1},%2;" : "=f"(lo), "=f"(hi) : "l"(v));
}
__device__ __forceinline__ u64 ffma2(u64 a, u64 b, u64 c) {
    u64 d; asm("fma.rn.f32x2 %0,%1,%2,%3;" : "=l"(d) : "l"(a), "l"(b), "l"(c)); return d;
}
__device__ __forceinline__ unsigned h2u(__half2 h) {
    return *reinterpret_cast<unsigned*>(&h);
}

// ------------------------------------------- zero counters + CSR cursor
__global__ void k_zero(int N4) {
    int i = blockIdx.x * blockDim.x + threadIdx.x;
    if (i < N4) reinterpret_cast<int4*>(g_cnt)[i] = make_int4(0, 0, 0, 0);
    if (i == 0) g_cursor = 0;
}

// ------------------------------------------------- in-degree count (int4 loads)
__global__ void k_count(const int* __restrict__ dst, int E) {
    int i = blockIdx.x * blockDim.x + threadIdx.x;
    int E4 = E >> 2;
    if (i < E4) {
        int4 d = reinterpret_cast<const int4*>(dst)[i];
        atomicAdd(&g_cnt[d.x], 1); atomicAdd(&g_cnt[d.y], 1);
        atomicAdd(&g_cnt[d.z], 1); atomicAdd(&g_cnt[d.w], 1);
    } else {
        int b = E4 * 4 + (i - E4);
        if (b < E) atomicAdd(&g_cnt[dst[b]], 1);
    }
}

// ---- single-kernel offsets: local scan + atomic region reservation + dis ----
__global__ __launch_bounds__(1024) void k_offs(int N) {
    __shared__ int s[1024];
    __shared__ int base_s;
    int tid = threadIdx.x;
    int i = blockIdx.x * 1024 + tid;
    int v = (i < N) ? g_cnt[i] : 0;
    s[tid] = v;
    __syncthreads();
    for (int off = 1; off < 1024; off <<= 1) {
        int t = (tid >= off) ? s[tid - off] : 0;
        __syncthreads();
        s[tid] += t;
        __syncthreads();
    }
    if (tid == 1023) base_s = atomicAdd(&g_cursor, s[1023]);
    __syncthreads();
    if (i < N) {
        int excl = s[tid] - v + base_s;
        g_off[i] = excl;
        g_cur[i] = excl;
        g_dis[i] = rsqrtf((float)v + 1.0f);
    }
}

// ---------------------------------------------------------------- CSR fill
__global__ void k_fill(const int* __restrict__ src, const int* __restrict__ dst, int E) {
    int i = blockIdx.x * blockDim.x + threadIdx.x;
    int E4 = E >> 2;
    if (i < E4) {
        int4 d = reinterpret_cast<const int4*>(dst)[i];
        int4 s = reinterpret_cast<const int4*>(src)[i];
        g_csr[atomicAdd(&g_cur[d.x], 1)] = s.x;
        g_csr[atomicAdd(&g_cur[d.y], 1)] = s.y;
        g_csr[atomicAdd(&g_cur[d.z], 1)] = s.z;
        g_csr[atomicAdd(&g_cur[d.w], 1)] = s.w;
    } else {
        int b = E4 * 4 + (i - E4);
        if (b < E) g_csr[atomicAdd(&g_cur[dst[b]], 1)] = src[b];
    }
}

// - h1' = fp16( dis * (x @ W1) ); const-mem weights, self-computed dis, 2 nodes/thr
__global__ __launch_bounds__(256) void k_gemm1(const float* __restrict__ x, int N) {
    int i0 = (blockIdx.x * blockDim.x + threadIdx.x) * 2;
    if (i0 >= N) return;
    int i1 = i0 + 1;
    bool has1 = i1 < N;

    const float4* xr0 = reinterpret_cast<const float4*>(x + (size_t)i0 * F_IN);
    const float4* xr1 = reinterpret_cast<const float4*>(x + (size_t)(has1 ? i1 : i0) * F_IN);
    u64 accA[F_H1 / 2], accB[F_H1 / 2];
#pragma unroll
    for (int j = 0; j < F_H1 / 2; j++) { accA[j] = 0ull; accB[j] = 0ull; }
#pragma unroll
    for (int k4 = 0; k4 < F_IN / 4; k4++) {
        float4 xa = xr0[k4], xb = xr1[k4];
        float as[4] = {xa.x, xa.y, xa.z, xa.w};
        float bs[4] = {xb.x, xb.y, xb.z, xb.w};
#pragma unroll
        for (int kk = 0; kk < 4; kk++) {
            int k = k4 * 4 + kk;
            u64 ab = pack2(as[kk], as[kk]);
            u64 bb = pack2(bs[kk], bs[kk]);
#pragma unroll
            for (int j = 0; j < F_H1 / 2; j++) {
                u64 w = c_W1p[k * (F_H1 / 2) + j];   // constant port, off the L1 path
                accA[j] = ffma2(ab, w, accA[j]);
                accB[j] = ffma2(bb, w, accB[j]);
            }
        }
    }
    float d0 = rsqrtf((float)__ldg(&g_cnt[i0]) + 1.0f);
    {
        __half2 h[8];
#pragma unroll
        for (int j = 0; j < 8; j++) {
            float lo, hi; unpack2(accA[j], lo, hi);
            h[j] = __floats2half2_rn(lo * d0, hi * d0);
        }
        uint4 o0, o1;
        o0.x = h2u(h[0]); o0.y = h2u(h[1]); o0.z = h2u(h[2]); o0.w = h2u(h[3]);
        o1.x = h2u(h[4]); o1.y = h2u(h[5]); o1.z = h2u(h[6]); o1.w = h2u(h[7]);
        g_h1h[(size_t)i0 * 2 + 0] = o0;
        g_h1h[(size_t)i0 * 2 + 1] = o1;
    }
    if (has1) {
        float d1 = rsqrtf((float)__ldg(&g_cnt[i1]) + 1.0f);
        __half2 h[8];
#pragma unroll
        for (int j = 0; j < 8; j++) {
            float lo, hi; unpack2(accB[j], lo, hi);
            h[j] = __floats2half2_rn(lo * d1, hi * d1);
        }
        uint4 o0, o1;
        o0.x = h2u(h[0]); o0.y = h2u(h[1]); o0.z = h2u(h[2]); o0.w = h2u(h[3]);
        o1.x = h2u(h[4]); o1.y = h2u(h[5]); o1.z = h2u(h[6]); o1.w = h2u(h[7]);
        g_h1h[(size_t)i1 * 2 + 0] = o0;
        g_h1h[(size_t)i1 * 2 + 1] = o1;
    }
}

__device__ __forceinline__ void acc8(float* acc, uint4 raw) {
    const __half2* hp = reinterpret_cast<const __half2*>(&raw);
#pragma unroll
    for (int q = 0; q < 4; q++) {
        float2 f = __half22float2(hp[q]);
        acc[2 * q]     += f.x;
        acc[2 * q + 1] += f.y;
    }
}
__device__ __forceinline__ void acc4(float* acc, uint2 raw) {
    const __half2* hp = reinterpret_cast<const __half2*>(&raw);
#pragma unroll
    for (int q = 0; q < 2; q++) {
        float2 f = __half22float2(hp[q]);
        acc[2 * q]     += f.x;
        acc[2 * q + 1] += f.y;
    }
}

// ---- layer-1 aggregation (fp16 gather) + epilogue + relu + GEMM2 fused ----
// 2 lanes per node; each lane owns 8 of the 16 features (one uint4 = 16B).
__global__ __launch_bounds__(256) void k_agg1(const float* __restrict__ b1,
                                              const float* __restrict__ W2, int N) {
    __shared__ float W2s[F_H1 * F_H2];
    __shared__ float b1s[F_H1];
    for (int t = threadIdx.x; t < F_H1 * F_H2; t += blockDim.x) W2s[t] = W2[t];
    if (threadIdx.x < F_H1) b1s[threadIdx.x] = b1[threadIdx.x];
    __syncthreads();

    int t = blockIdx.x * blockDim.x + threadIdx.x;
    int node = t >> 1, sub = t & 1;
    int nodec = node < N ? node : N - 1;     // keep full warp for shuffles

    int beg = __ldg(&g_off[nodec]), cnt = __ldg(&g_cnt[nodec]);
    float acc[8];
#pragma unroll
    for (int j = 0; j < 8; j++) acc[j] = 0.f;
    acc8(acc, __ldg(&g_h1h[(size_t)nodec * 2 + sub]));          // self loop

    int k = 0;
    for (; k + 4 <= cnt; k += 4) {
        int s0 = __ldg(&g_csr[beg + k]),     s1 = __ldg(&g_csr[beg + k + 1]);
        int s2 = __ldg(&g_csr[beg + k + 2]), s3 = __ldg(&g_csr[beg + k + 3]);
        uint4 v0 = __ldg(&g_h1h[(size_t)s0 * 2 + sub]);
        uint4 v1 = __ldg(&g_h1h[(size_t)s1 * 2 + sub]);
        uint4 v2 = __ldg(&g_h1h[(size_t)s2 * 2 + sub]);
        uint4 v3 = __ldg(&g_h1h[(size_t)s3 * 2 + sub]);
        acc8(acc, v0); acc8(acc, v1); acc8(acc, v2); acc8(acc, v3);
    }
    for (; k < cnt; k++) {
        int s = __ldg(&g_csr[beg + k]);
        acc8(acc, __ldg(&g_h1h[(size_t)s * 2 + sub]));
    }

    float dd = g_dis[nodec];
    float own[8];
#pragma unroll
    for (int j = 0; j < 8; j++)
        own[j] = fmaxf(acc[j] * dd + b1s[sub * 8 + j], 0.f);

    // exchange halves with partner lane (same node) -> full 16-vector
    float r[F_H1];
#pragma unroll
    for (int j = 0; j < 8; j++) {
        float oth = __shfl_xor_sync(0xffffffffu, own[j], 1);
        r[sub * 8 + j]       = own[j];
        r[(sub ^ 1) * 8 + j] = oth;
    }
    // each lane computes 4 of the 8 GEMM2 outputs, scaled by dis, packed fp16
    float o[4];
#pragma unroll
    for (int q = 0; q < 4; q++) o[q] = 0.f;
#pragma unroll
    for (int j = 0; j < F_H1; j++) {
#pragma unroll
        for (int q = 0; q < 4; q++)
            o[q] += r[j] * W2s[j * F_H2 + sub * 4 + q];
    }
    if (node < N) {
        uint2 w;
        w.x = h2u(__floats2half2_rn(o[0] * dd, o[1] * dd));
        w.y = h2u(__floats2half2_rn(o[2] * dd, o[3] * dd));
        g_h2h[(size_t)node * 2 + sub] = w;
    }
}

// ---- layer-2 aggregation (fp16 gather, 2 lanes/node) + epilogue + relu ----
__global__ __launch_bounds__(256) void k_agg2(const float* __restrict__ b2, int N) {
    __shared__ float b2s[F_H2];
    if (threadIdx.x < F_H2) b2s[threadIdx.x] = b2[threadIdx.x];
    __syncthreads();
    int t = blockIdx.x * blockDim.x + threadIdx.x;
    int node = t >> 1, sub = t & 1;
    if (node >= N) return;
    int beg = __ldg(&g_off[node]), cnt = __ldg(&g_cnt[node]);
    float acc[4];
#pragma unroll
    for (int j = 0; j < 4; j++) acc[j] = 0.f;
    acc4(acc, __ldg(&g_h2h[(size_t)node * 2 + sub]));           // self loop
    int k = 0;
    for (; k + 4 <= cnt; k += 4) {
        int s0 = __ldg(&g_csr[beg + k]),     s1 = __ldg(&g_csr[beg + k + 1]);
        int s2 = __ldg(&g_csr[beg + k + 2]), s3 = __ldg(&g_csr[beg + k + 3]);
        uint2 v0 = __ldg(&g_h2h[(size_t)s0 * 2 + sub]);
        uint2 v1 = __ldg(&g_h2h[(size_t)s1 * 2 + sub]);
        uint2 v2 = __ldg(&g_h2h[(size_t)s2 * 2 + sub]);
        uint2 v3 = __ldg(&g_h2h[(size_t)s3 * 2 + sub]);
        acc4(acc, v0); acc4(acc, v1); acc4(acc, v2); acc4(acc, v3);
    }
    for (; k < cnt; k++) {
        int s = __ldg(&g_csr[beg + k]);
        acc4(acc, __ldg(&g_h2h[(size_t)s * 2 + sub]));
    }
    float dd = g_dis[node];
    float4 o;
    o.x = fmaxf(acc[0] * dd + b2s[sub * 4 + 0], 0.f);
    o.y = fmaxf(acc[1] * dd + b2s[sub * 4 + 1], 0.f);
    o.z = fmaxf(acc[2] * dd + b2s[sub * 4 + 2], 0.f);
    o.w = fmaxf(acc[3] * dd + b2s[sub * 4 + 3], 0.f);
    *reinterpret_cast<float4*>(&g_f[(size_t)node * F_H2 + sub * 4]) = o;
}

// ---------------- mean pool (warp per graph, sorted batch) + linear head ----
__global__ __launch_bounds__(256) void k_pool(const int* __restrict__ batch,
                                              const float* __restrict__ Wl,
                                              const float* __restrict__ bl,
                                              float* __restrict__ out, int N, int G) {
    int gw   = (blockIdx.x * blockDim.x + threadIdx.x) >> 5;
    int lane = threadIdx.x & 31;
    if (gw >= G) return;

    int lo = 0, hi = N;
    while (lo < hi) { int m = (lo + hi) >> 1; if (batch[m] <  gw) lo = m + 1; else hi = m; }
    int beg = lo;
    lo = beg; hi = N;
    while (lo < hi) { int m = (lo + hi) >> 1; if (batch[m] <= gw) lo = m + 1; else hi = m; }
    int end = lo;

    float acc[F_H2];
#pragma unroll
    for (int j = 0; j < F_H2; j++) acc[j] = 0.f;

    for (int i = beg + lane; i < end; i += 32) {
        const float4* f4 = reinterpret_cast<const float4*>(&g_f[(size_t)i * F_H2]);
        float4 a = f4[0], b = f4[1];
        acc[0] += a.x; acc[1] += a.y; acc[2] += a.z; acc[3] += a.w;
        acc[4] += b.x; acc[5] += b.y; acc[6] += b.z; acc[7] += b.w;
    }
#pragma unroll
    for (int j = 0; j < F_H2; j++)
#pragma unroll
        for (int off = 16; off; off >>= 1)
            acc[j] += __shfl_xor_sync(0xffffffffu, acc[j], off);

    float inv = 1.0f / fmaxf((float)(end - beg), 1.0f);
    if (lane < N_CLS) {
        float o = bl[lane];
#pragma unroll
        for (int j = 0; j < F_H2; j++) o += (acc[j] * inv) * Wl[j * N_CLS + lane];
        out[(size_t)gw * N_CLS + lane] = o;
    }
}

// ---------------------------------------------------------------- launch
extern "C" void kernel_launch(void* const* d_in, const int* in_sizes, int n_in,
                              void* d_out, int out_size) {
    const float* x     = (const float*)d_in[0];
    const int*   ei    = (const int*)  d_in[1];
    const int*   batch = (const int*)  d_in[2];
    int base = (n_in >= 10 && in_sizes[3] <= 4) ? 4 : 3;
    const float* W1 = (const float*)d_in[base + 0];
    const float* b1 = (const float*)d_in[base + 1];
    const float* W2 = (const float*)d_in[base + 2];
    const float* b2 = (const float*)d_in[base + 3];
    const float* Wl = (const float*)d_in[base + 4];
    const float* bl = (const float*)d_in[base + 5];
    float* out = (float*)d_out;

    int N = in_sizes[2];
    int E = in_sizes[1] / 2;
    int G = out_size / N_CLS;
    const int* src = ei;
    const int* dst = ei + E;

    // one-time host-side resources for the fork-join (no device memory)
    static cudaStream_t s2 = nullptr;
    static cudaEvent_t evA = nullptr, evB = nullptr;
    if (!s2) {
        cudaStreamCreateWithFlags(&s2, cudaStreamNonBlocking);
        cudaEventCreateWithFlags(&evA, cudaEventDisableTiming);
        cudaEventCreateWithFlags(&evB, cudaEventDisableTiming);
    }

    const int T = 256;
    int N4   = (N + 3) / 4;
    int E4   = (E >> 2) + 4;                 // vec body + scalar tail threads
    int ebv  = (E4 + T - 1) / T;
    int NB   = (N + 1023) / 1024;

    // main chain: zero -> count -> (fork) -> offs -> fill
    k_zero <<<(N4 + T - 1) / T, T>>>(N4);
    k_count<<<ebv, T>>>(dst, E);

    cudaEventRecord(evA, 0);
    cudaStreamWaitEvent(s2, evA, 0);
    // side chain (needs only counts + c_W1p): gemm1 (computes its own dis)
    cudaMemcpyToSymbolAsync(c_W1p, W1, F_IN * F_H1 * sizeof(float), 0,
                            cudaMemcpyDeviceToDevice, s2);
    k_gemm1<<<(N + 511) / 512, T, 0, s2>>>(x, N);
    cudaEventRecord(evB, s2);

    k_offs<<<NB, 1024>>>(N);
    k_fill<<<ebv, T>>>(src, dst, E);

    // join: aggregation needs both CSR (main) and h1 (side)
    cudaStreamWaitEvent(0, evB, 0);
    k_agg1<<<((size_t)N * 2 + T - 1) / T, T>>>(b1, W2, N);
    k_agg2<<<((size_t)N * 2 + T - 1) / T, T>>>(b2, N);
    k_pool<<<((size_t)G * 32 + T - 1) / T, T>>>(batch, Wl, bl, out, N, G);
}

// round 16
// speedup vs baseline: 1.0422x; 1.0122x over previous
#include <cuda_runtime.h>
#include <cuda_fp16.h>
#include <math.h>

#define F_IN  32
#define F_H1  16
#define F_H2  8
#define N_CLS 5
#define MAX_N 1048576
#define MAX_E 16000000

typedef unsigned long long u64;

// ---- scratch (__device__ globals; allocation-free rule) ----
__device__ __align__(16) int   g_cnt[MAX_N];          // in-degree
__device__ __align__(16) int   g_off[MAX_N];          // CSR offsets
__device__ __align__(16) int   g_cur[MAX_N];          // fill cursors
__device__ __align__(16) float g_dis[MAX_N];          // rsqrt(deg+1)
__device__ __align__(16) int   g_csr[MAX_E];          // src ids bucketed by dst (dense)
__device__ int g_cursor;                              // CSR region cursor
__device__ __align__(16) uint4 g_h1h[MAX_N * 2];      // fp16: dis*(x@W1), 32B/row
__device__ __align__(16) uint2 g_h2h[MAX_N * 2];      // fp16: dis*(relu(conv1)@W2), 16B/row
__device__ __align__(16) uint2 g_fh [MAX_N * 2];      // fp16: relu(conv2), 16B/row

__constant__ u64 c_W1p[F_IN * F_H1 / 2];              // W1 as packed f32 pairs

__device__ __forceinline__ u64 pack2(float lo, float hi) {
    u64 r; asm("mov.b64 %0,{%1,%2};" : "=l"(r) : "f"(lo), "f"(hi)); return r;
}
__device__ __forceinline__ void unpack2(u64 v, float& lo, float& hi) {
    asm("mov.b64 {%0,%1},%2;" : "=f"(lo), "=f"(hi) : "l"(v));
}
__device__ __forceinline__ u64 ffma2(u64 a, u64 b, u64 c) {
    u64 d; asm("fma.rn.f32x2 %0,%1,%2,%3;" : "=l"(d) : "l"(a), "l"(b), "l"(c)); return d;
}
__device__ __forceinline__ unsigned h2u(__half2 h) {
    return *reinterpret_cast<unsigned*>(&h);
}

// ------------------------------------------- zero counters + CSR cursor
__global__ void k_zero(int N4) {
    int i = blockIdx.x * blockDim.x + threadIdx.x;
    if (i < N4) reinterpret_cast<int4*>(g_cnt)[i] = make_int4(0, 0, 0, 0);
    if (i == 0) g_cursor = 0;
}

// ------------------------------------------------- in-degree count (int4 loads)
__global__ void k_count(const int* __restrict__ dst, int E) {
    int i = blockIdx.x * blockDim.x + threadIdx.x;
    int E4 = E >> 2;
    if (i < E4) {
        int4 d = reinterpret_cast<const int4*>(dst)[i];
        atomicAdd(&g_cnt[d.x], 1); atomicAdd(&g_cnt[d.y], 1);
        atomicAdd(&g_cnt[d.z], 1); atomicAdd(&g_cnt[d.w], 1);
    } else {
        int b = E4 * 4 + (i - E4);
        if (b < E) atomicAdd(&g_cnt[dst[b]], 1);
    }
}

// ---- single-kernel offsets: local scan + atomic region reservation + dis ----
__global__ __launch_bounds__(1024) void k_offs(int N) {
    __shared__ int s[1024];
    __shared__ int base_s;
    int tid = threadIdx.x;
    int i = blockIdx.x * 1024 + tid;
    int v = (i < N) ? g_cnt[i] : 0;
    s[tid] = v;
    __syncthreads();
    for (int off = 1; off < 1024; off <<= 1) {
        int t = (tid >= off) ? s[tid - off] : 0;
        __syncthreads();
        s[tid] += t;
        __syncthreads();
    }
    if (tid == 1023) base_s = atomicAdd(&g_cursor, s[1023]);
    __syncthreads();
    if (i < N) {
        int excl = s[tid] - v + base_s;
        g_off[i] = excl;
        g_cur[i] = excl;
        g_dis[i] = rsqrtf((float)v + 1.0f);
    }
}

// ---------------------------------------------------------------- CSR fill
__global__ void k_fill(const int* __restrict__ src, const int* __restrict__ dst, int E) {
    int i = blockIdx.x * blockDim.x + threadIdx.x;
    int E4 = E >> 2;
    if (i < E4) {
        int4 d = reinterpret_cast<const int4*>(dst)[i];
        int4 s = reinterpret_cast<const int4*>(src)[i];
        g_csr[atomicAdd(&g_cur[d.x], 1)] = s.x;
        g_csr[atomicAdd(&g_cur[d.y], 1)] = s.y;
        g_csr[atomicAdd(&g_cur[d.z], 1)] = s.z;
        g_csr[atomicAdd(&g_cur[d.w], 1)] = s.w;
    } else {
        int b = E4 * 4 + (i - E4);
        if (b < E) g_csr[atomicAdd(&g_cur[dst[b]], 1)] = src[b];
    }
}

// - h1' = fp16( dis * (x @ W1) ); const-mem weights, self-computed dis, 2 nodes/thr
__global__ __launch_bounds__(256) void k_gemm1(const float* __restrict__ x, int N) {
    int i0 = (blockIdx.x * blockDim.x + threadIdx.x) * 2;
    if (i0 >= N) return;
    int i1 = i0 + 1;
    bool has1 = i1 < N;

    const float4* xr0 = reinterpret_cast<const float4*>(x + (size_t)i0 * F_IN);
    const float4* xr1 = reinterpret_cast<const float4*>(x + (size_t)(has1 ? i1 : i0) * F_IN);
    u64 accA[F_H1 / 2], accB[F_H1 / 2];
#pragma unroll
    for (int j = 0; j < F_H1 / 2; j++) { accA[j] = 0ull; accB[j] = 0ull; }
#pragma unroll
    for (int k4 = 0; k4 < F_IN / 4; k4++) {
        float4 xa = xr0[k4], xb = xr1[k4];
        float as[4] = {xa.x, xa.y, xa.z, xa.w};
        float bs[4] = {xb.x, xb.y, xb.z, xb.w};
#pragma unroll
        for (int kk = 0; kk < 4; kk++) {
            int k = k4 * 4 + kk;
            u64 ab = pack2(as[kk], as[kk]);
            u64 bb = pack2(bs[kk], bs[kk]);
#pragma unroll
            for (int j = 0; j < F_H1 / 2; j++) {
                u64 w = c_W1p[k * (F_H1 / 2) + j];   // constant port, off the L1 path
                accA[j] = ffma2(ab, w, accA[j]);
                accB[j] = ffma2(bb, w, accB[j]);
            }
        }
    }
    float d0 = rsqrtf((float)__ldg(&g_cnt[i0]) + 1.0f);
    {
        __half2 h[8];
#pragma unroll
        for (int j = 0; j < 8; j++) {
            float lo, hi; unpack2(accA[j], lo, hi);
            h[j] = __floats2half2_rn(lo * d0, hi * d0);
        }
        uint4 o0, o1;
        o0.x = h2u(h[0]); o0.y = h2u(h[1]); o0.z = h2u(h[2]); o0.w = h2u(h[3]);
        o1.x = h2u(h[4]); o1.y = h2u(h[5]); o1.z = h2u(h[6]); o1.w = h2u(h[7]);
        g_h1h[(size_t)i0 * 2 + 0] = o0;
        g_h1h[(size_t)i0 * 2 + 1] = o1;
    }
    if (has1) {
        float d1 = rsqrtf((float)__ldg(&g_cnt[i1]) + 1.0f);
        __half2 h[8];
#pragma unroll
        for (int j = 0; j < 8; j++) {
            float lo, hi; unpack2(accB[j], lo, hi);
            h[j] = __floats2half2_rn(lo * d1, hi * d1);
        }
        uint4 o0, o1;
        o0.x = h2u(h[0]); o0.y = h2u(h[1]); o0.z = h2u(h[2]); o0.w = h2u(h[3]);
        o1.x = h2u(h[4]); o1.y = h2u(h[5]); o1.z = h2u(h[6]); o1.w = h2u(h[7]);
        g_h1h[(size_t)i1 * 2 + 0] = o0;
        g_h1h[(size_t)i1 * 2 + 1] = o1;
    }
}

__device__ __forceinline__ void acc8(float* acc, uint4 raw) {
    const __half2* hp = reinterpret_cast<const __half2*>(&raw);
#pragma unroll
    for (int q = 0; q < 4; q++) {
        float2 f = __half22float2(hp[q]);
        acc[2 * q]     += f.x;
        acc[2 * q + 1] += f.y;
    }
}
__device__ __forceinline__ void acc4(float* acc, uint2 raw) {
    const __half2* hp = reinterpret_cast<const __half2*>(&raw);
#pragma unroll
    for (int q = 0; q < 2; q++) {
        float2 f = __half22float2(hp[q]);
        acc[2 * q]     += f.x;
        acc[2 * q + 1] += f.y;
    }
}

// ---- layer-1 aggregation (fp16 gather, 8-deep MLP) + relu + GEMM2 fused ----
// 2 lanes per node; each lane owns 8 of the 16 features (one uint4 = 16B).
__global__ __launch_bounds__(256) void k_agg1(const float* __restrict__ b1,
                                              const float* __restrict__ W2, int N) {
    __shared__ float W2s[F_H1 * F_H2];
    __shared__ float b1s[F_H1];
    for (int t = threadIdx.x; t < F_H1 * F_H2; t += blockDim.x) W2s[t] = W2[t];
    if (threadIdx.x < F_H1) b1s[threadIdx.x] = b1[threadIdx.x];
    __syncthreads();

    int t = blockIdx.x * blockDim.x + threadIdx.x;
    int node = t >> 1, sub = t & 1;
    int nodec = node < N ? node : N - 1;     // keep full warp for shuffles

    int beg = __ldg(&g_off[nodec]), cnt = __ldg(&g_cnt[nodec]);
    float acc[8];
#pragma unroll
    for (int j = 0; j < 8; j++) acc[j] = 0.f;
    acc8(acc, __ldg(&g_h1h[(size_t)nodec * 2 + sub]));          // self loop

    int k = 0;
    for (; k + 8 <= cnt; k += 8) {
        int si[8];
#pragma unroll
        for (int u = 0; u < 8; u++) si[u] = __ldg(&g_csr[beg + k + u]);
        uint4 v[8];
#pragma unroll
        for (int u = 0; u < 8; u++) v[u] = __ldg(&g_h1h[(size_t)si[u] * 2 + sub]);
#pragma unroll
        for (int u = 0; u < 8; u++) acc8(acc, v[u]);
    }
    for (; k + 4 <= cnt; k += 4) {
        int s0 = __ldg(&g_csr[beg + k]),     s1 = __ldg(&g_csr[beg + k + 1]);
        int s2 = __ldg(&g_csr[beg + k + 2]), s3 = __ldg(&g_csr[beg + k + 3]);
        uint4 v0 = __ldg(&g_h1h[(size_t)s0 * 2 + sub]);
        uint4 v1 = __ldg(&g_h1h[(size_t)s1 * 2 + sub]);
        uint4 v2 = __ldg(&g_h1h[(size_t)s2 * 2 + sub]);
        uint4 v3 = __ldg(&g_h1h[(size_t)s3 * 2 + sub]);
        acc8(acc, v0); acc8(acc, v1); acc8(acc, v2); acc8(acc, v3);
    }
    for (; k < cnt; k++) {
        int s = __ldg(&g_csr[beg + k]);
        acc8(acc, __ldg(&g_h1h[(size_t)s * 2 + sub]));
    }

    float dd = g_dis[nodec];
    float own[8];
#pragma unroll
    for (int j = 0; j < 8; j++)
        own[j] = fmaxf(acc[j] * dd + b1s[sub * 8 + j], 0.f);

    // exchange halves with partner lane (same node) -> full 16-vector
    float r[F_H1];
#pragma unroll
    for (int j = 0; j < 8; j++) {
        float oth = __shfl_xor_sync(0xffffffffu, own[j], 1);
        r[sub * 8 + j]       = own[j];
        r[(sub ^ 1) * 8 + j] = oth;
    }
    // each lane computes 4 of the 8 GEMM2 outputs, scaled by dis, packed fp16
    float o[4];
#pragma unroll
    for (int q = 0; q < 4; q++) o[q] = 0.f;
#pragma unroll
    for (int j = 0; j < F_H1; j++) {
#pragma unroll
        for (int q = 0; q < 4; q++)
            o[q] += r[j] * W2s[j * F_H2 + sub * 4 + q];
    }
    if (node < N) {
        uint2 w;
        w.x = h2u(__floats2half2_rn(o[0] * dd, o[1] * dd));
        w.y = h2u(__floats2half2_rn(o[2] * dd, o[3] * dd));
        g_h2h[(size_t)node * 2 + sub] = w;
    }
}

// ---- layer-2 aggregation (fp16 gather, 8-deep MLP) + epilogue + relu ----
__global__ __launch_bounds__(256) void k_agg2(const float* __restrict__ b2, int N) {
    __shared__ float b2s[F_H2];
    if (threadIdx.x < F_H2) b2s[threadIdx.x] = b2[threadIdx.x];
    __syncthreads();
    int t = blockIdx.x * blockDim.x + threadIdx.x;
    int node = t >> 1, sub = t & 1;
    if (node >= N) return;
    int beg = __ldg(&g_off[node]), cnt = __ldg(&g_cnt[node]);
    float acc[4];
#pragma unroll
    for (int j = 0; j < 4; j++) acc[j] = 0.f;
    acc4(acc, __ldg(&g_h2h[(size_t)node * 2 + sub]));           // self loop
    int k = 0;
    for (; k + 8 <= cnt; k += 8) {
        int si[8];
#pragma unroll
        for (int u = 0; u < 8; u++) si[u] = __ldg(&g_csr[beg + k + u]);
        uint2 v[8];
#pragma unroll
        for (int u = 0; u < 8; u++) v[u] = __ldg(&g_h2h[(size_t)si[u] * 2 + sub]);
#pragma unroll
        for (int u = 0; u < 8; u++) acc4(acc, v[u]);
    }
    for (; k + 4 <= cnt; k += 4) {
        int s0 = __ldg(&g_csr[beg + k]),     s1 = __ldg(&g_csr[beg + k + 1]);
        int s2 = __ldg(&g_csr[beg + k + 2]), s3 = __ldg(&g_csr[beg + k + 3]);
        uint2 v0 = __ldg(&g_h2h[(size_t)s0 * 2 + sub]);
        uint2 v1 = __ldg(&g_h2h[(size_t)s1 * 2 + sub]);
        uint2 v2 = __ldg(&g_h2h[(size_t)s2 * 2 + sub]);
        uint2 v3 = __ldg(&g_h2h[(size_t)s3 * 2 + sub]);
        acc4(acc, v0); acc4(acc, v1); acc4(acc, v2); acc4(acc, v3);
    }
    for (; k < cnt; k++) {
        int s = __ldg(&g_csr[beg + k]);
        acc4(acc, __ldg(&g_h2h[(size_t)s * 2 + sub]));
    }
    float dd = g_dis[node];
    uint2 o;
    o.x = h2u(__floats2half2_rn(fmaxf(acc[0] * dd + b2s[sub * 4 + 0], 0.f),
                                fmaxf(acc[1] * dd + b2s[sub * 4 + 1], 0.f)));
    o.y = h2u(__floats2half2_rn(fmaxf(acc[2] * dd + b2s[sub * 4 + 2], 0.f),
                                fmaxf(acc[3] * dd + b2s[sub * 4 + 3], 0.f)));
    g_fh[(size_t)node * 2 + sub] = o;
}

// ---------------- mean pool (warp per graph, sorted batch) + linear head ----
__global__ __launch_bounds__(256) void k_pool(const int* __restrict__ batch,
                                              const float* __restrict__ Wl,
                                              const float* __restrict__ bl,
                                              float* __restrict__ out, int N, int G) {
    int gw   = (blockIdx.x * blockDim.x + threadIdx.x) >> 5;
    int lane = threadIdx.x & 31;
    if (gw >= G) return;

    int lo = 0, hi = N;
    while (lo < hi) { int m = (lo + hi) >> 1; if (batch[m] <  gw) lo = m + 1; else hi = m; }
    int beg = lo;
    lo = beg; hi = N;
    while (lo < hi) { int m = (lo + hi) >> 1; if (batch[m] <= gw) lo = m + 1; else hi = m; }
    int end = lo;

    float acc[F_H2];
#pragma unroll
    for (int j = 0; j < F_H2; j++) acc[j] = 0.f;

    const uint4* fh = reinterpret_cast<const uint4*>(g_fh);
    for (int i = beg + lane; i < end; i += 32) {
        acc8(acc, __ldg(&fh[i]));
    }
#pragma unroll
    for (int j = 0; j < F_H2; j++)
#pragma unroll
        for (int off = 16; off; off >>= 1)
            acc[j] += __shfl_xor_sync(0xffffffffu, acc[j], off);

    float inv = 1.0f / fmaxf((float)(end - beg), 1.0f);
    if (lane < N_CLS) {
        float o = bl[lane];
#pragma unroll
        for (int j = 0; j < F_H2; j++) o += (acc[j] * inv) * Wl[j * N_CLS + lane];
        out[(size_t)gw * N_CLS + lane] = o;
    }
}

// ---------------------------------------------------------------- launch
extern "C" void kernel_launch(void* const* d_in, const int* in_sizes, int n_in,
                              void* d_out, int out_size) {
    const float* x     = (const float*)d_in[0];
    const int*   ei    = (const int*)  d_in[1];
    const int*   batch = (const int*)  d_in[2];
    int base = (n_in >= 10 && in_sizes[3] <= 4) ? 4 : 3;
    const float* W1 = (const float*)d_in[base + 0];
    const float* b1 = (const float*)d_in[base + 1];
    const float* W2 = (const float*)d_in[base + 2];
    const float* b2 = (const float*)d_in[base + 3];
    const float* Wl = (const float*)d_in[base + 4];
    const float* bl = (const float*)d_in[base + 5];
    float* out = (float*)d_out;

    int N = in_sizes[2];
    int E = in_sizes[1] / 2;
    int G = out_size / N_CLS;
    const int* src = ei;
    const int* dst = ei + E;

    // one-time host-side resources for the fork-join (no device memory)
    static cudaStream_t s2 = nullptr;
    static cudaEvent_t evA = nullptr, evB = nullptr;
    if (!s2) {
        cudaStreamCreateWithFlags(&s2, cudaStreamNonBlocking);
        cudaEventCreateWithFlags(&evA, cudaEventDisableTiming);
        cudaEventCreateWithFlags(&evB, cudaEventDisableTiming);
    }

    const int T = 256;
    int N4   = (N + 3) / 4;
    int E4   = (E >> 2) + 4;                 // vec body + scalar tail threads
    int ebv  = (E4 + T - 1) / T;
    int NB   = (N + 1023) / 1024;

    // main chain: zero -> count -> (fork) -> offs -> fill
    k_zero <<<(N4 + T - 1) / T, T>>>(N4);
    k_count<<<ebv, T>>>(dst, E);

    cudaEventRecord(evA, 0);
    cudaStreamWaitEvent(s2, evA, 0);
    // side chain (needs only counts + c_W1p): gemm1 (computes its own dis)
    cudaMemcpyToSymbolAsync(c_W1p, W1, F_IN * F_H1 * sizeof(float), 0,
                            cudaMemcpyDeviceToDevice, s2);
    k_gemm1<<<(N + 511) / 512, T, 0, s2>>>(x, N);
    cudaEventRecord(evB, s2);

    k_offs<<<NB, 1024>>>(N);
    k_fill<<<ebv, T>>>(src, dst, E);

    // join: aggregation needs both CSR (main) and h1 (side)
    cudaStreamWaitEvent(0, evB, 0);
    k_agg1<<<((size_t)N * 2 + T - 1) / T, T>>>(b1, W2, N);
    k_agg2<<<((size_t)N * 2 + T - 1) / T, T>>>(b2, N);
    k_pool<<<((size_t)G * 32 + T - 1) / T, T>>>(batch, Wl, bl, out, N, G);
}